// round 1
// baseline (speedup 1.0000x reference)
#include <cuda_runtime.h>

#define TT 128
#define FF 64
#define HH 128
#define NROW 8192   // B*A*T

__device__ float g_wt_buf[NROW * FF];   // softmax gate weights [row][f]

// ---------------------------------------------------------------------------
// Kernel 1: gating network + softmax over time.
// One block per (b,a): x,s tiles are [T=128, F=64].
//   G1 = elu(x@w1 + s@w2 + b1 + b2)      [128,128]
//   G  = G1@w3 + b3                       [128,64]
//   w_t = softmax over t (per column f)  -> g_wt_buf
// ---------------------------------------------------------------------------
__global__ __launch_bounds__(256) void gating_kernel(
    const float* __restrict__ x, const float* __restrict__ s,
    const float* __restrict__ w1, const float* __restrict__ b1,
    const float* __restrict__ w2, const float* __restrict__ b2,
    const float* __restrict__ w3, const float* __restrict__ b3)
{
    extern __shared__ float sm[];
    float* sm0 = sm;          // xs[t*64+f] (8192) + ss (8192); later G1 [h*129 + t] (16512)
    float* smG = sm + 16512;  // 8192: G [t*64+f]
    const int tid = threadIdx.x;
    const int blk = blockIdx.x;      // 0..63 = b*8+a
    const int ty = tid >> 4;         // 0..15
    const int tx = tid & 15;         // 0..15

    // load x,s tiles
    {
        const float4* xb4 = (const float4*)(x + blk * (TT * FF));
        const float4* sb4 = (const float4*)(s + blk * (TT * FF));
        float4* sm04 = (float4*)sm0;
        #pragma unroll
        for (int i = 0; i < 8; i++) {
            sm04[tid + i * 256]        = xb4[tid + i * 256];
            sm04[2048 + tid + i * 256] = sb4[tid + i * 256];
        }
    }
    __syncthreads();

    // Phase B: G1[t,h] with 8x8 micro-tiles (rows ty*8.., cols tx*8..)
    float acc[8][8];
    #pragma unroll
    for (int i = 0; i < 8; i++)
        #pragma unroll
        for (int j = 0; j < 8; j++) acc[i][j] = 0.f;

    for (int f = 0; f < FF; f++) {
        float xa[8], sa[8];
        #pragma unroll
        for (int i = 0; i < 8; i++) {
            xa[i] = sm0[(ty * 8 + i) * FF + f];
            sa[i] = sm0[8192 + (ty * 8 + i) * FF + f];
        }
        float4 wa = *(const float4*)(w1 + f * HH + tx * 8);
        float4 wb = *(const float4*)(w1 + f * HH + tx * 8 + 4);
        float4 va = *(const float4*)(w2 + f * HH + tx * 8);
        float4 vb = *(const float4*)(w2 + f * HH + tx * 8 + 4);
        float wv[8] = {wa.x, wa.y, wa.z, wa.w, wb.x, wb.y, wb.z, wb.w};
        float vv[8] = {va.x, va.y, va.z, va.w, vb.x, vb.y, vb.z, vb.w};
        #pragma unroll
        for (int i = 0; i < 8; i++)
            #pragma unroll
            for (int j = 0; j < 8; j++)
                acc[i][j] += xa[i] * wv[j] + sa[i] * vv[j];
    }
    // bias + elu
    {
        float bsum[8];
        #pragma unroll
        for (int j = 0; j < 8; j++) bsum[j] = b1[tx * 8 + j] + b2[tx * 8 + j];
        #pragma unroll
        for (int i = 0; i < 8; i++)
            #pragma unroll
            for (int j = 0; j < 8; j++) {
                float v = acc[i][j] + bsum[j];
                acc[i][j] = v > 0.f ? v : (__expf(v) - 1.f);
            }
    }
    __syncthreads();   // all reads of xs/ss done
    // store G1 transposed: [h][t], pitch 129
    #pragma unroll
    for (int i = 0; i < 8; i++)
        #pragma unroll
        for (int j = 0; j < 8; j++)
            sm0[(tx * 8 + j) * 129 + ty * 8 + i] = acc[i][j];
    __syncthreads();

    // Phase C: G = G1 @ w3 + b3  (rows ty*8.., cols tx*4..)
    float acc2[8][4];
    #pragma unroll
    for (int i = 0; i < 8; i++)
        #pragma unroll
        for (int j = 0; j < 4; j++) acc2[i][j] = 0.f;
    for (int h = 0; h < HH; h++) {
        float4 w3v = *(const float4*)(w3 + h * FF + tx * 4);
        float wv[4] = {w3v.x, w3v.y, w3v.z, w3v.w};
        float a[8];
        #pragma unroll
        for (int i = 0; i < 8; i++) a[i] = sm0[h * 129 + ty * 8 + i];
        #pragma unroll
        for (int i = 0; i < 8; i++)
            #pragma unroll
            for (int j = 0; j < 4; j++) acc2[i][j] += a[i] * wv[j];
    }
    {
        float b3v[4];
        #pragma unroll
        for (int j = 0; j < 4; j++) b3v[j] = b3[tx * 4 + j];
        #pragma unroll
        for (int i = 0; i < 8; i++)
            #pragma unroll
            for (int j = 0; j < 4; j++)
                smG[(ty * 8 + i) * FF + tx * 4 + j] = acc2[i][j] + b3v[j];
    }
    __syncthreads();

    // Phase D: softmax over t per column f (thread tid = f handles one column)
    if (tid < FF) {
        float m = -1e30f;
        for (int t = 0; t < TT; t++) m = fmaxf(m, smG[t * FF + tid]);
        float ssum = 0.f;
        for (int t = 0; t < TT; t++) {
            float e = __expf(smG[t * FF + tid] - m);
            smG[t * FF + tid] = e;
            ssum += e;
        }
        float r = 1.f / ssum;
        for (int t = 0; t < TT; t++)
            g_wt_buf[(blk * TT + t) * FF + tid] = smG[t * FF + tid] * r;
    }
}

// ---------------------------------------------------------------------------
// Kernel 2: out[r,k] = sum_f sum_h (w_t[r,f]*elu(x[r,f]*jw1[f,h]+jb1[f,h]))*jw3[f,h,k]
//                    + sum_f w_t[r,f]*jb3[f,k]
// Grid 128 (64 rows each), 256 threads, 4x8 micro-tiles, 64x128x128 smem GEMM
// per f.
// ---------------------------------------------------------------------------
__global__ __launch_bounds__(256) void combine_kernel(
    const float* __restrict__ x,
    const float* __restrict__ jw1, const float* __restrict__ jb1,
    const float* __restrict__ jw3, const float* __restrict__ jb3,
    float* __restrict__ out)
{
    extern __shared__ float sm[];
    float* Asm = sm;                 // 8192  : A tile transposed [h*64 + r]
    float* Bsm = sm + 8192;          // 16384 : jw3[f] slab [h*128 + k]
    float* j1  = sm + 24576;         // 128   : jw1 row f
    float* jbr = sm + 24704;         // 128   : jb1 row f
    float* xs  = sm + 24832;         // 4096  : x tile transposed [f*64 + r]
    float* wts = sm + 28928;         // 4096  : w_t tile transposed [f*64 + r]

    const int tid = threadIdx.x;
    const int blk = blockIdx.x;      // 0..127
    const int rbase = blk * 64;
    const int r0 = tid & 63;
    const int hb = tid >> 6;         // 0..3
    const int ty = tid >> 4;         // 0..15 -> rows ty*4..
    const int tx = tid & 15;         // 0..15 -> cols tx*8..

    // stage x and w_t tiles (transposed so per-f column reads are conflict-free)
    #pragma unroll
    for (int i = 0; i < 4; i++) {
        int q  = tid + i * 256;      // float4 index 0..1023
        int r  = q >> 4;             // row 0..63
        int fs = q & 15;             // f-segment 0..15
        float4 xv = *(const float4*)(x        + (rbase + r) * FF + fs * 4);
        float4 wv = *(const float4*)(g_wt_buf + (rbase + r) * FF + fs * 4);
        xs[(fs * 4 + 0) * 64 + r] = xv.x;
        xs[(fs * 4 + 1) * 64 + r] = xv.y;
        xs[(fs * 4 + 2) * 64 + r] = xv.z;
        xs[(fs * 4 + 3) * 64 + r] = xv.w;
        wts[(fs * 4 + 0) * 64 + r] = wv.x;
        wts[(fs * 4 + 1) * 64 + r] = wv.y;
        wts[(fs * 4 + 2) * 64 + r] = wv.z;
        wts[(fs * 4 + 3) * 64 + r] = wv.w;
    }

    float acc[4][8];
    #pragma unroll
    for (int i = 0; i < 4; i++)
        #pragma unroll
        for (int j = 0; j < 8; j++) acc[i][j] = 0.f;

    for (int f = 0; f < FF; f++) {
        __syncthreads();   // prev GEMM reads done (and staging visible on f=0)
        // stage jw1/jb1 row
        if (tid < 128) {
            j1[tid]  = jw1[f * HH + tid];
            jbr[tid] = jb1[f * HH + tid];
        }
        // stage jw3[f] slab: 16384 floats
        {
            const float4* src = (const float4*)(jw3 + f * HH * HH);
            float4* dst = (float4*)Bsm;
            #pragma unroll
            for (int i = 0; i < 16; i++)
                dst[tid + i * 256] = src[tid + i * 256];
        }
        // jb3 term: acc += w_t[r,f] * jb3[f,k]
        {
            float4 ja = *(const float4*)(jb3 + f * HH + tx * 8);
            float4 jb4 = *(const float4*)(jb3 + f * HH + tx * 8 + 4);
            float jv[8] = {ja.x, ja.y, ja.z, ja.w, jb4.x, jb4.y, jb4.z, jb4.w};
            #pragma unroll
            for (int i = 0; i < 4; i++) {
                float wt = wts[f * 64 + ty * 4 + i];
                #pragma unroll
                for (int j = 0; j < 8; j++) acc[i][j] += wt * jv[j];
            }
        }
        __syncthreads();   // j1/jbr/Bsm visible
        // build A tile: Asm[h][r] = w_t[r,f] * elu(x[r,f]*jw1[f,h] + jb1[f,h])
        {
            float xv = xs[f * 64 + r0];
            float wt = wts[f * 64 + r0];
            #pragma unroll
            for (int hh = 0; hh < 32; hh++) {
                int h = hb * 32 + hh;
                float v = fmaf(xv, j1[h], jbr[h]);
                float e = v > 0.f ? v : (__expf(v) - 1.f);
                Asm[h * 64 + r0] = wt * e;
            }
        }
        __syncthreads();   // A tile visible
        // 64x128x128 GEMM accumulate
        {
            const float4* A4 = (const float4*)Asm;
            const float4* B4 = (const float4*)Bsm;
            #pragma unroll 4
            for (int h = 0; h < HH; h++) {
                float4 a4  = A4[h * 16 + ty];
                float4 b0  = B4[h * 32 + tx * 2];
                float4 b1v = B4[h * 32 + tx * 2 + 1];
                float av[4] = {a4.x, a4.y, a4.z, a4.w};
                float bv[8] = {b0.x, b0.y, b0.z, b0.w, b1v.x, b1v.y, b1v.z, b1v.w};
                #pragma unroll
                for (int i = 0; i < 4; i++)
                    #pragma unroll
                    for (int j = 0; j < 8; j++)
                        acc[i][j] += av[i] * bv[j];
            }
        }
    }

    // write output [row][k]
    #pragma unroll
    for (int i = 0; i < 4; i++) {
        float4 o0 = make_float4(acc[i][0], acc[i][1], acc[i][2], acc[i][3]);
        float4 o1 = make_float4(acc[i][4], acc[i][5], acc[i][6], acc[i][7]);
        *(float4*)(out + (rbase + ty * 4 + i) * HH + tx * 8)     = o0;
        *(float4*)(out + (rbase + ty * 4 + i) * HH + tx * 8 + 4) = o1;
    }
}

extern "C" void kernel_launch(void* const* d_in, const int* in_sizes, int n_in,
                              void* d_out, int out_size) {
    const float* x   = (const float*)d_in[0];
    const float* s   = (const float*)d_in[1];
    const float* w1  = (const float*)d_in[2];
    const float* b1  = (const float*)d_in[3];
    const float* w2  = (const float*)d_in[4];
    const float* b2  = (const float*)d_in[5];
    const float* w3  = (const float*)d_in[6];
    const float* b3  = (const float*)d_in[7];
    const float* jw1 = (const float*)d_in[8];
    const float* jb1 = (const float*)d_in[9];
    const float* jw3 = (const float*)d_in[10];
    const float* jb3 = (const float*)d_in[11];
    float* out = (float*)d_out;

    const int smem1 = (16512 + 8192) * 4;   // 98816 B
    const int smem2 = (8192 + 16384 + 128 + 128 + 4096 + 4096) * 4;  // 132096 B
    cudaFuncSetAttribute(gating_kernel,  cudaFuncAttributeMaxDynamicSharedMemorySize, smem1);
    cudaFuncSetAttribute(combine_kernel, cudaFuncAttributeMaxDynamicSharedMemorySize, smem2);

    gating_kernel<<<64, 256, smem1>>>(x, s, w1, b1, w2, b2, w3, b3);
    combine_kernel<<<128, 256, smem2>>>(x, jw1, jb1, jw3, jb3, out);
}

// round 2
// speedup vs baseline: 1.6129x; 1.6129x over previous
#include <cuda_runtime.h>

#define TT 128
#define FF 64
#define HH 128
#define NROW 8192   // B*A*T
#define FH 32       // f per combine-CTA (f-split in 2)

__device__ float g_wt_buf[NROW * FF];   // softmax gate weights [row][f]
__device__ float g_part[NROW * HH];     // partial output from f-half 1

// ---- packed fp32x2 helpers (Blackwell FFMA2) --------------------------------
__device__ __forceinline__ void ffma2(unsigned long long& d,
                                      unsigned long long a,
                                      unsigned long long b) {
    asm("fma.rn.f32x2 %0, %1, %2, %0;" : "+l"(d) : "l"(a), "l"(b));
}
__device__ __forceinline__ unsigned long long pack2(float v) {
    unsigned long long r;
    asm("mov.b64 %0, {%1, %1};" : "=l"(r) : "f"(v));
    return r;
}
__device__ __forceinline__ void unpack2(unsigned long long v, float& lo, float& hi) {
    asm("mov.b64 {%0, %1}, %2;" : "=f"(lo), "=f"(hi) : "l"(v));
}

// ---------------------------------------------------------------------------
// Kernel 1: gating network + softmax over time. One block per (b,a).
// ---------------------------------------------------------------------------
__global__ __launch_bounds__(256) void gating_kernel(
    const float* __restrict__ x, const float* __restrict__ s,
    const float* __restrict__ w1, const float* __restrict__ b1,
    const float* __restrict__ w2, const float* __restrict__ b2,
    const float* __restrict__ w3, const float* __restrict__ b3)
{
    extern __shared__ float sm[];
    float* sm0 = sm;          // xs(8192)+ss(8192); later G1 [h*129+t]
    float* smG = sm + 16512;  // 8192: G [t*64+f]
    const int tid = threadIdx.x;
    const int blk = blockIdx.x;
    const int ty = tid >> 4;
    const int tx = tid & 15;

    {
        const float4* xb4 = (const float4*)(x + blk * (TT * FF));
        const float4* sb4 = (const float4*)(s + blk * (TT * FF));
        float4* sm04 = (float4*)sm0;
        #pragma unroll
        for (int i = 0; i < 8; i++) {
            sm04[tid + i * 256]        = xb4[tid + i * 256];
            sm04[2048 + tid + i * 256] = sb4[tid + i * 256];
        }
    }
    __syncthreads();

    float acc[8][8];
    #pragma unroll
    for (int i = 0; i < 8; i++)
        #pragma unroll
        for (int j = 0; j < 8; j++) acc[i][j] = 0.f;

    for (int f = 0; f < FF; f++) {
        float xa[8], sa[8];
        #pragma unroll
        for (int i = 0; i < 8; i++) {
            xa[i] = sm0[(ty * 8 + i) * FF + f];
            sa[i] = sm0[8192 + (ty * 8 + i) * FF + f];
        }
        float4 wa = *(const float4*)(w1 + f * HH + tx * 8);
        float4 wb = *(const float4*)(w1 + f * HH + tx * 8 + 4);
        float4 va = *(const float4*)(w2 + f * HH + tx * 8);
        float4 vb = *(const float4*)(w2 + f * HH + tx * 8 + 4);
        float wv[8] = {wa.x, wa.y, wa.z, wa.w, wb.x, wb.y, wb.z, wb.w};
        float vv[8] = {va.x, va.y, va.z, va.w, vb.x, vb.y, vb.z, vb.w};
        #pragma unroll
        for (int i = 0; i < 8; i++)
            #pragma unroll
            for (int j = 0; j < 8; j++)
                acc[i][j] += xa[i] * wv[j] + sa[i] * vv[j];
    }
    {
        float bsum[8];
        #pragma unroll
        for (int j = 0; j < 8; j++) bsum[j] = b1[tx * 8 + j] + b2[tx * 8 + j];
        #pragma unroll
        for (int i = 0; i < 8; i++)
            #pragma unroll
            for (int j = 0; j < 8; j++) {
                float v = acc[i][j] + bsum[j];
                acc[i][j] = v > 0.f ? v : (__expf(v) - 1.f);
            }
    }
    __syncthreads();
    #pragma unroll
    for (int i = 0; i < 8; i++)
        #pragma unroll
        for (int j = 0; j < 8; j++)
            sm0[(tx * 8 + j) * 129 + ty * 8 + i] = acc[i][j];
    __syncthreads();

    float acc2[8][4];
    #pragma unroll
    for (int i = 0; i < 8; i++)
        #pragma unroll
        for (int j = 0; j < 4; j++) acc2[i][j] = 0.f;
    for (int h = 0; h < HH; h++) {
        float4 w3v = *(const float4*)(w3 + h * FF + tx * 4);
        float wv[4] = {w3v.x, w3v.y, w3v.z, w3v.w};
        float a[8];
        #pragma unroll
        for (int i = 0; i < 8; i++) a[i] = sm0[h * 129 + ty * 8 + i];
        #pragma unroll
        for (int i = 0; i < 8; i++)
            #pragma unroll
            for (int j = 0; j < 4; j++) acc2[i][j] += a[i] * wv[j];
    }
    {
        float b3v[4];
        #pragma unroll
        for (int j = 0; j < 4; j++) b3v[j] = b3[tx * 4 + j];
        #pragma unroll
        for (int i = 0; i < 8; i++)
            #pragma unroll
            for (int j = 0; j < 4; j++)
                smG[(ty * 8 + i) * FF + tx * 4 + j] = acc2[i][j] + b3v[j];
    }
    __syncthreads();

    if (tid < FF) {
        float m = -1e30f;
        for (int t = 0; t < TT; t++) m = fmaxf(m, smG[t * FF + tid]);
        float ssum = 0.f;
        for (int t = 0; t < TT; t++) {
            float e = __expf(smG[t * FF + tid] - m);
            smG[t * FF + tid] = e;
            ssum += e;
        }
        float r = 1.f / ssum;
        for (int t = 0; t < TT; t++)
            g_wt_buf[(blk * TT + t) * FF + tid] = smG[t * FF + tid] * r;
    }
}

// ---------------------------------------------------------------------------
// Kernel 2: softmax-gated per-feature FFN combine, f-split into 2 halves.
// CTA = (row_tile 0..63, half 0..1): 128 rows x 128 cols output tile,
// f in [half*32, half*32+32). 256 threads, 8x8 micro-tiles, FFMA2 inner loop.
// half 0 -> out, half 1 -> g_part.
// ---------------------------------------------------------------------------
__global__ __launch_bounds__(256) void combine_kernel(
    const float* __restrict__ x,
    const float* __restrict__ jw1, const float* __restrict__ jb1,
    const float* __restrict__ jw3, const float* __restrict__ jb3,
    float* __restrict__ out)
{
    extern __shared__ float sm[];
    float* Asm = sm;                 // 16384 : A tile [h*128 + r]
    float* Bsm = sm + 16384;         // 16384 : jw3[f] slab [h*128 + k]
    float* xs  = sm + 32768;         // 4096  : x tile [fl*128 + r]
    float* wts = sm + 36864;         // 4096  : w_t tile [fl*128 + r]
    float* j1  = sm + 40960;         // 128
    float* jbr = sm + 41088;         // 128

    const int tid = threadIdx.x;
    const int blk = blockIdx.x;      // 0..127
    const int rt = blk >> 1;
    const int half = blk & 1;
    const int rbase = rt * 128;
    const int fbase = half * FH;
    float* dst = half ? g_part : out;

    const int ty = tid >> 4;         // 0..15 -> rows ty*8..
    const int tx = tid & 15;         // 0..15 -> cols tx*8..

    // stage x and w_t tiles transposed: [f_local][r]
    #pragma unroll
    for (int i = 0; i < 4; i++) {
        int q  = tid + i * 256;      // 0..1023
        int r  = q >> 3;             // 0..127
        int fs = q & 7;              // 0..7
        float4 xv = *(const float4*)(x        + (rbase + r) * FF + fbase + fs * 4);
        float4 wv = *(const float4*)(g_wt_buf + (rbase + r) * FF + fbase + fs * 4);
        xs[(fs * 4 + 0) * 128 + r] = xv.x;
        xs[(fs * 4 + 1) * 128 + r] = xv.y;
        xs[(fs * 4 + 2) * 128 + r] = xv.z;
        xs[(fs * 4 + 3) * 128 + r] = xv.w;
        wts[(fs * 4 + 0) * 128 + r] = wv.x;
        wts[(fs * 4 + 1) * 128 + r] = wv.y;
        wts[(fs * 4 + 2) * 128 + r] = wv.z;
        wts[(fs * 4 + 3) * 128 + r] = wv.w;
    }

    // accumulators: 4 row-pairs x 8 cols, packed fp32x2 (row-pair in lo/hi)
    unsigned long long acc[4][8];
    #pragma unroll
    for (int i = 0; i < 4; i++)
        #pragma unroll
        for (int j = 0; j < 8; j++) acc[i][j] = 0ull;

    // A-build thread mapping: 4 consecutive rows x 16 h per thread
    const int br4 = (tid & 31) * 4;  // rows br4..br4+3
    const int bhb = tid >> 5;        // h = bhb*16 .. +16

    for (int fl = 0; fl < FH; fl++) {
        const int f = fbase + fl;
        __syncthreads();   // prev-iter reads done; staging visible on fl=0

        if (tid < 128) {
            j1[tid]  = jw1[f * HH + tid];
            jbr[tid] = jb1[f * HH + tid];
        }
        {   // stage jw3[f] slab: 16384 floats
            const float4* src = (const float4*)(jw3 + f * HH * HH);
            float4* dst4 = (float4*)Bsm;
            #pragma unroll
            for (int i = 0; i < 16; i++)
                dst4[tid + i * 256] = src[tid + i * 256];
        }
        {   // jb3 term: acc += w_t[r,f] * jb3[f,k]  (packed over row pairs)
            float4 ja  = *(const float4*)(jb3 + f * HH + tx * 8);
            float4 jb4 = *(const float4*)(jb3 + f * HH + tx * 8 + 4);
            float jv[8] = {ja.x, ja.y, ja.z, ja.w, jb4.x, jb4.y, jb4.z, jb4.w};
            unsigned long long jp[8];
            #pragma unroll
            for (int j = 0; j < 8; j++) jp[j] = pack2(jv[j]);
            const ulonglong2* W2 = (const ulonglong2*)wts;
            ulonglong2 w0 = W2[fl * 32 + ty * 2];
            ulonglong2 w1v = W2[fl * 32 + ty * 2 + 1];
            unsigned long long wp[4] = {w0.x, w0.y, w1v.x, w1v.y};
            #pragma unroll
            for (int i = 0; i < 4; i++)
                #pragma unroll
                for (int j = 0; j < 8; j++) ffma2(acc[i][j], wp[i], jp[j]);
        }
        __syncthreads();   // staging visible

        // build A tile: Asm[h][r] = w_t[r,f] * elu(x[r,f]*jw1[f,h] + jb1[f,h])
        {
            float4 xv = *(const float4*)(xs  + fl * 128 + br4);
            float4 wv = *(const float4*)(wts + fl * 128 + br4);
            #pragma unroll
            for (int hh = 0; hh < 16; hh++) {
                int h = bhb * 16 + hh;
                float w = j1[h], b = jbr[h];
                float4 v;
                float t0 = fmaf(xv.x, w, b);
                float t1 = fmaf(xv.y, w, b);
                float t2 = fmaf(xv.z, w, b);
                float t3 = fmaf(xv.w, w, b);
                v.x = (t0 > 0.f ? t0 : (__expf(t0) - 1.f)) * wv.x;
                v.y = (t1 > 0.f ? t1 : (__expf(t1) - 1.f)) * wv.y;
                v.z = (t2 > 0.f ? t2 : (__expf(t2) - 1.f)) * wv.z;
                v.w = (t3 > 0.f ? t3 : (__expf(t3) - 1.f)) * wv.w;
                *(float4*)(Asm + h * 128 + br4) = v;
            }
        }
        __syncthreads();   // A visible

        // 128x128x128 GEMM accumulate, FFMA2 inner loop
        {
            const ulonglong2* A2 = (const ulonglong2*)Asm;
            const float4*     B4 = (const float4*)Bsm;
            #pragma unroll 4
            for (int h = 0; h < HH; h++) {
                ulonglong2 a0 = A2[h * 32 + ty * 2];
                ulonglong2 a1 = A2[h * 32 + ty * 2 + 1];
                unsigned long long ap[4] = {a0.x, a0.y, a1.x, a1.y};
                float4 b0 = B4[h * 32 + tx * 2];
                float4 b1v = B4[h * 32 + tx * 2 + 1];
                float bs[8] = {b0.x, b0.y, b0.z, b0.w, b1v.x, b1v.y, b1v.z, b1v.w};
                unsigned long long bp[8];
                #pragma unroll
                for (int j = 0; j < 8; j++) bp[j] = pack2(bs[j]);
                #pragma unroll
                for (int i = 0; i < 4; i++)
                    #pragma unroll
                    for (int j = 0; j < 8; j++)
                        ffma2(acc[i][j], ap[i], bp[j]);
            }
        }
    }

    // epilogue: unpack row pairs, write 128-col rows
    #pragma unroll
    for (int i = 0; i < 4; i++) {
        float lo[8], hi[8];
        #pragma unroll
        for (int j = 0; j < 8; j++) unpack2(acc[i][j], lo[j], hi[j]);
        int row0 = rbase + ty * 8 + i * 2;
        *(float4*)(dst + row0 * HH + tx * 8)           = make_float4(lo[0], lo[1], lo[2], lo[3]);
        *(float4*)(dst + row0 * HH + tx * 8 + 4)       = make_float4(lo[4], lo[5], lo[6], lo[7]);
        *(float4*)(dst + (row0 + 1) * HH + tx * 8)     = make_float4(hi[0], hi[1], hi[2], hi[3]);
        *(float4*)(dst + (row0 + 1) * HH + tx * 8 + 4) = make_float4(hi[4], hi[5], hi[6], hi[7]);
    }
}

// out += g_part
__global__ __launch_bounds__(256) void add_kernel(float* __restrict__ out) {
    int i = blockIdx.x * 256 + threadIdx.x;   // float4 index
    float4 a = ((const float4*)out)[i];
    float4 b = ((const float4*)g_part)[i];
    ((float4*)out)[i] = make_float4(a.x + b.x, a.y + b.y, a.z + b.z, a.w + b.w);
}

extern "C" void kernel_launch(void* const* d_in, const int* in_sizes, int n_in,
                              void* d_out, int out_size) {
    const float* x   = (const float*)d_in[0];
    const float* s   = (const float*)d_in[1];
    const float* w1  = (const float*)d_in[2];
    const float* b1  = (const float*)d_in[3];
    const float* w2  = (const float*)d_in[4];
    const float* b2  = (const float*)d_in[5];
    const float* w3  = (const float*)d_in[6];
    const float* b3  = (const float*)d_in[7];
    const float* jw1 = (const float*)d_in[8];
    const float* jb1 = (const float*)d_in[9];
    const float* jw3 = (const float*)d_in[10];
    const float* jb3 = (const float*)d_in[11];
    float* out = (float*)d_out;

    const int smem1 = (16512 + 8192) * 4;                       // 98816 B
    const int smem2 = (16384 + 16384 + 4096 + 4096 + 256) * 4;  // 164864 B
    cudaFuncSetAttribute(gating_kernel,  cudaFuncAttributeMaxDynamicSharedMemorySize, smem1);
    cudaFuncSetAttribute(combine_kernel, cudaFuncAttributeMaxDynamicSharedMemorySize, smem2);

    gating_kernel<<<64, 256, smem1>>>(x, s, w1, b1, w2, b2, w3, b3);
    combine_kernel<<<128, 256, smem2>>>(x, jw1, jb1, jw3, jb3, out);
    add_kernel<<<NROW * HH / 4 / 256, 256>>>(out);
}

// round 3
// speedup vs baseline: 1.6151x; 1.0013x over previous
#include <cuda_runtime.h>

#define TT 128
#define FF 64
#define HH 128
#define NROW 8192   // B*A*T
#define FH 32       // f per combine-CTA (f-split in 2)

__device__ float g_wt_buf[NROW * FF];   // softmax gate weights [row][f]
__device__ float g_part[NROW * HH];     // partial output from f-half 1

// ---- packed fp32x2 helpers (Blackwell FFMA2) --------------------------------
__device__ __forceinline__ void ffma2(unsigned long long& d,
                                      unsigned long long a,
                                      unsigned long long b) {
    asm("fma.rn.f32x2 %0, %1, %2, %0;" : "+l"(d) : "l"(a), "l"(b));
}
__device__ __forceinline__ unsigned long long pack2(float v) {
    unsigned long long r;
    asm("mov.b64 %0, {%1, %1};" : "=l"(r) : "f"(v));
    return r;
}
__device__ __forceinline__ void unpack2(unsigned long long v, float& lo, float& hi) {
    asm("mov.b64 {%0, %1}, %2;" : "=f"(lo), "=f"(hi) : "l"(v));
}

// ---------------------------------------------------------------------------
// Kernel 1: gating network + softmax over time. One block per (b,a).
// ---------------------------------------------------------------------------
__global__ __launch_bounds__(256) void gating_kernel(
    const float* __restrict__ x, const float* __restrict__ s,
    const float* __restrict__ w1, const float* __restrict__ b1,
    const float* __restrict__ w2, const float* __restrict__ b2,
    const float* __restrict__ w3, const float* __restrict__ b3)
{
    extern __shared__ float sm[];
    float* sm0 = sm;          // xs(8192)+ss(8192); later G1 [h*129+t]
    float* smG = sm + 16512;  // 8192: G [t*64+f]
    const int tid = threadIdx.x;
    const int blk = blockIdx.x;
    const int ty = tid >> 4;
    const int tx = tid & 15;

    {
        const float4* xb4 = (const float4*)(x + blk * (TT * FF));
        const float4* sb4 = (const float4*)(s + blk * (TT * FF));
        float4* sm04 = (float4*)sm0;
        #pragma unroll
        for (int i = 0; i < 8; i++) {
            sm04[tid + i * 256]        = xb4[tid + i * 256];
            sm04[2048 + tid + i * 256] = sb4[tid + i * 256];
        }
    }
    __syncthreads();

    float acc[8][8];
    #pragma unroll
    for (int i = 0; i < 8; i++)
        #pragma unroll
        for (int j = 0; j < 8; j++) acc[i][j] = 0.f;

    for (int f = 0; f < FF; f++) {
        float xa[8], sa[8];
        #pragma unroll
        for (int i = 0; i < 8; i++) {
            xa[i] = sm0[(ty * 8 + i) * FF + f];
            sa[i] = sm0[8192 + (ty * 8 + i) * FF + f];
        }
        float4 wa = *(const float4*)(w1 + f * HH + tx * 8);
        float4 wb = *(const float4*)(w1 + f * HH + tx * 8 + 4);
        float4 va = *(const float4*)(w2 + f * HH + tx * 8);
        float4 vb = *(const float4*)(w2 + f * HH + tx * 8 + 4);
        float wv[8] = {wa.x, wa.y, wa.z, wa.w, wb.x, wb.y, wb.z, wb.w};
        float vv[8] = {va.x, va.y, va.z, va.w, vb.x, vb.y, vb.z, vb.w};
        #pragma unroll
        for (int i = 0; i < 8; i++)
            #pragma unroll
            for (int j = 0; j < 8; j++)
                acc[i][j] += xa[i] * wv[j] + sa[i] * vv[j];
    }
    {
        float bsum[8];
        #pragma unroll
        for (int j = 0; j < 8; j++) bsum[j] = b1[tx * 8 + j] + b2[tx * 8 + j];
        #pragma unroll
        for (int i = 0; i < 8; i++)
            #pragma unroll
            for (int j = 0; j < 8; j++) {
                float v = acc[i][j] + bsum[j];
                acc[i][j] = v > 0.f ? v : (__expf(v) - 1.f);
            }
    }
    __syncthreads();
    #pragma unroll
    for (int i = 0; i < 8; i++)
        #pragma unroll
        for (int j = 0; j < 8; j++)
            sm0[(tx * 8 + j) * 129 + ty * 8 + i] = acc[i][j];
    __syncthreads();

    float acc2[8][4];
    #pragma unroll
    for (int i = 0; i < 8; i++)
        #pragma unroll
        for (int j = 0; j < 4; j++) acc2[i][j] = 0.f;
    for (int h = 0; h < HH; h++) {
        float4 w3v = *(const float4*)(w3 + h * FF + tx * 4);
        float wv[4] = {w3v.x, w3v.y, w3v.z, w3v.w};
        float a[8];
        #pragma unroll
        for (int i = 0; i < 8; i++) a[i] = sm0[h * 129 + ty * 8 + i];
        #pragma unroll
        for (int i = 0; i < 8; i++)
            #pragma unroll
            for (int j = 0; j < 4; j++) acc2[i][j] += a[i] * wv[j];
    }
    {
        float b3v[4];
        #pragma unroll
        for (int j = 0; j < 4; j++) b3v[j] = b3[tx * 4 + j];
        #pragma unroll
        for (int i = 0; i < 8; i++)
            #pragma unroll
            for (int j = 0; j < 4; j++)
                smG[(ty * 8 + i) * FF + tx * 4 + j] = acc2[i][j] + b3v[j];
    }
    __syncthreads();

    if (tid < FF) {
        float m = -1e30f;
        for (int t = 0; t < TT; t++) m = fmaxf(m, smG[t * FF + tid]);
        float ssum = 0.f;
        for (int t = 0; t < TT; t++) {
            float e = __expf(smG[t * FF + tid] - m);
            smG[t * FF + tid] = e;
            ssum += e;
        }
        float r = 1.f / ssum;
        for (int t = 0; t < TT; t++)
            g_wt_buf[(blk * TT + t) * FF + tid] = smG[t * FF + tid] * r;
    }
}

// ---------------------------------------------------------------------------
// Kernel 2: softmax-gated per-feature FFN combine, f-split into 2 halves.
// CTA = (row_tile 0..63, half 0..1): 128 rows x 128 cols output tile,
// f in [half*32, half*32+32). 256 threads, 8x8 micro-tiles, FFMA2 inner loop.
// half 0 -> out, half 1 -> g_part.
// ---------------------------------------------------------------------------
__global__ __launch_bounds__(256) void combine_kernel(
    const float* __restrict__ x,
    const float* __restrict__ jw1, const float* __restrict__ jb1,
    const float* __restrict__ jw3, const float* __restrict__ jb3,
    float* __restrict__ out)
{
    extern __shared__ float sm[];
    float* Asm = sm;                 // 16384 : A tile [h*128 + r]
    float* Bsm = sm + 16384;         // 16384 : jw3[f] slab [h*128 + k]
    float* xs  = sm + 32768;         // 4096  : x tile [fl*128 + r]
    float* wts = sm + 36864;         // 4096  : w_t tile [fl*128 + r]
    float* j1  = sm + 40960;         // 128
    float* jbr = sm + 41088;         // 128

    const int tid = threadIdx.x;
    const int blk = blockIdx.x;      // 0..127
    const int rt = blk >> 1;
    const int half = blk & 1;
    const int rbase = rt * 128;
    const int fbase = half * FH;
    float* dst = half ? g_part : out;

    const int ty = tid >> 4;         // 0..15 -> rows ty*8..
    const int tx = tid & 15;         // 0..15 -> cols tx*8..

    // stage x and w_t tiles transposed: [f_local][r]
    #pragma unroll
    for (int i = 0; i < 4; i++) {
        int q  = tid + i * 256;      // 0..1023
        int r  = q >> 3;             // 0..127
        int fs = q & 7;              // 0..7
        float4 xv = *(const float4*)(x        + (rbase + r) * FF + fbase + fs * 4);
        float4 wv = *(const float4*)(g_wt_buf + (rbase + r) * FF + fbase + fs * 4);
        xs[(fs * 4 + 0) * 128 + r] = xv.x;
        xs[(fs * 4 + 1) * 128 + r] = xv.y;
        xs[(fs * 4 + 2) * 128 + r] = xv.z;
        xs[(fs * 4 + 3) * 128 + r] = xv.w;
        wts[(fs * 4 + 0) * 128 + r] = wv.x;
        wts[(fs * 4 + 1) * 128 + r] = wv.y;
        wts[(fs * 4 + 2) * 128 + r] = wv.z;
        wts[(fs * 4 + 3) * 128 + r] = wv.w;
    }

    // accumulators: 4 row-pairs x 8 cols, packed fp32x2 (row-pair in lo/hi)
    unsigned long long acc[4][8];
    #pragma unroll
    for (int i = 0; i < 4; i++)
        #pragma unroll
        for (int j = 0; j < 8; j++) acc[i][j] = 0ull;

    // A-build thread mapping: 4 consecutive rows x 16 h per thread
    const int br4 = (tid & 31) * 4;  // rows br4..br4+3
    const int bhb = tid >> 5;        // h = bhb*16 .. +16

    for (int fl = 0; fl < FH; fl++) {
        const int f = fbase + fl;
        __syncthreads();   // prev-iter reads done; staging visible on fl=0

        if (tid < 128) {
            j1[tid]  = jw1[f * HH + tid];
            jbr[tid] = jb1[f * HH + tid];
        }
        {   // stage jw3[f] slab: 16384 floats
            const float4* src = (const float4*)(jw3 + f * HH * HH);
            float4* dst4 = (float4*)Bsm;
            #pragma unroll
            for (int i = 0; i < 16; i++)
                dst4[tid + i * 256] = src[tid + i * 256];
        }
        {   // jb3 term: acc += w_t[r,f] * jb3[f,k]  (packed over row pairs)
            float4 ja  = *(const float4*)(jb3 + f * HH + tx * 8);
            float4 jb4 = *(const float4*)(jb3 + f * HH + tx * 8 + 4);
            float jv[8] = {ja.x, ja.y, ja.z, ja.w, jb4.x, jb4.y, jb4.z, jb4.w};
            unsigned long long jp[8];
            #pragma unroll
            for (int j = 0; j < 8; j++) jp[j] = pack2(jv[j]);
            const ulonglong2* W2 = (const ulonglong2*)wts;
            ulonglong2 w0 = W2[fl * 32 + ty * 2];
            ulonglong2 w1v = W2[fl * 32 + ty * 2 + 1];
            unsigned long long wp[4] = {w0.x, w0.y, w1v.x, w1v.y};
            #pragma unroll
            for (int i = 0; i < 4; i++)
                #pragma unroll
                for (int j = 0; j < 8; j++) ffma2(acc[i][j], wp[i], jp[j]);
        }
        __syncthreads();   // staging visible

        // build A tile: Asm[h][r] = w_t[r,f] * elu(x[r,f]*jw1[f,h] + jb1[f,h])
        {
            float4 xv = *(const float4*)(xs  + fl * 128 + br4);
            float4 wv = *(const float4*)(wts + fl * 128 + br4);
            #pragma unroll
            for (int hh = 0; hh < 16; hh++) {
                int h = bhb * 16 + hh;
                float w = j1[h], b = jbr[h];
                float4 v;
                float t0 = fmaf(xv.x, w, b);
                float t1 = fmaf(xv.y, w, b);
                float t2 = fmaf(xv.z, w, b);
                float t3 = fmaf(xv.w, w, b);
                v.x = (t0 > 0.f ? t0 : (__expf(t0) - 1.f)) * wv.x;
                v.y = (t1 > 0.f ? t1 : (__expf(t1) - 1.f)) * wv.y;
                v.z = (t2 > 0.f ? t2 : (__expf(t2) - 1.f)) * wv.z;
                v.w = (t3 > 0.f ? t3 : (__expf(t3) - 1.f)) * wv.w;
                *(float4*)(Asm + h * 128 + br4) = v;
            }
        }
        __syncthreads();   // A visible

        // 128x128x128 GEMM accumulate, FFMA2 inner loop
        {
            const ulonglong2* A2 = (const ulonglong2*)Asm;
            const float4*     B4 = (const float4*)Bsm;
            #pragma unroll 4
            for (int h = 0; h < HH; h++) {
                ulonglong2 a0 = A2[h * 32 + ty * 2];
                ulonglong2 a1 = A2[h * 32 + ty * 2 + 1];
                unsigned long long ap[4] = {a0.x, a0.y, a1.x, a1.y};
                float4 b0 = B4[h * 32 + tx * 2];
                float4 b1v = B4[h * 32 + tx * 2 + 1];
                float bs[8] = {b0.x, b0.y, b0.z, b0.w, b1v.x, b1v.y, b1v.z, b1v.w};
                unsigned long long bp[8];
                #pragma unroll
                for (int j = 0; j < 8; j++) bp[j] = pack2(bs[j]);
                #pragma unroll
                for (int i = 0; i < 4; i++)
                    #pragma unroll
                    for (int j = 0; j < 8; j++)
                        ffma2(acc[i][j], ap[i], bp[j]);
            }
        }
    }

    // epilogue: unpack row pairs, write 128-col rows
    #pragma unroll
    for (int i = 0; i < 4; i++) {
        float lo[8], hi[8];
        #pragma unroll
        for (int j = 0; j < 8; j++) unpack2(acc[i][j], lo[j], hi[j]);
        int row0 = rbase + ty * 8 + i * 2;
        *(float4*)(dst + row0 * HH + tx * 8)           = make_float4(lo[0], lo[1], lo[2], lo[3]);
        *(float4*)(dst + row0 * HH + tx * 8 + 4)       = make_float4(lo[4], lo[5], lo[6], lo[7]);
        *(float4*)(dst + (row0 + 1) * HH + tx * 8)     = make_float4(hi[0], hi[1], hi[2], hi[3]);
        *(float4*)(dst + (row0 + 1) * HH + tx * 8 + 4) = make_float4(hi[4], hi[5], hi[6], hi[7]);
    }
}

// out += g_part
__global__ __launch_bounds__(256) void add_kernel(float* __restrict__ out) {
    int i = blockIdx.x * 256 + threadIdx.x;   // float4 index
    float4 a = ((const float4*)out)[i];
    float4 b = ((const float4*)g_part)[i];
    ((float4*)out)[i] = make_float4(a.x + b.x, a.y + b.y, a.z + b.z, a.w + b.w);
}

extern "C" void kernel_launch(void* const* d_in, const int* in_sizes, int n_in,
                              void* d_out, int out_size) {
    const float* x   = (const float*)d_in[0];
    const float* s   = (const float*)d_in[1];
    const float* w1  = (const float*)d_in[2];
    const float* b1  = (const float*)d_in[3];
    const float* w2  = (const float*)d_in[4];
    const float* b2  = (const float*)d_in[5];
    const float* w3  = (const float*)d_in[6];
    const float* b3  = (const float*)d_in[7];
    const float* jw1 = (const float*)d_in[8];
    const float* jb1 = (const float*)d_in[9];
    const float* jw3 = (const float*)d_in[10];
    const float* jb3 = (const float*)d_in[11];
    float* out = (float*)d_out;

    const int smem1 = (16512 + 8192) * 4;                       // 98816 B
    const int smem2 = (16384 + 16384 + 4096 + 4096 + 256) * 4;  // 164864 B
    cudaFuncSetAttribute(gating_kernel,  cudaFuncAttributeMaxDynamicSharedMemorySize, smem1);
    cudaFuncSetAttribute(combine_kernel, cudaFuncAttributeMaxDynamicSharedMemorySize, smem2);

    gating_kernel<<<64, 256, smem1>>>(x, s, w1, b1, w2, b2, w3, b3);
    combine_kernel<<<128, 256, smem2>>>(x, jw1, jb1, jw3, jb3, out);
    add_kernel<<<NROW * HH / 4 / 256, 256>>>(out);
}

// round 6
// speedup vs baseline: 3.9162x; 2.4247x over previous
#include <cuda_runtime.h>
#include <cuda_fp16.h>
#include <stdint.h>

#define FF 64
#define HH 128
#define NROW 8192
#define FH 32
#define BPITCH 272            // bytes per 128-elem fp16 row (16B padded)
#define SLAB 34816            // 128 rows * 272 B

__device__ float g_gbuf[NROW * FF];     // raw gating logits
__device__ float g_wt_buf[NROW * FF];   // softmaxed gates
__device__ float g_part[NROW * HH];     // f-half-1 partial
__device__ __align__(16) unsigned char g_Bt[FF * SLAB];  // jw3^T fp16 [f][k][h]

// ---------------- helpers ----------------
__device__ __forceinline__ uint32_t smem_u32(const void* p) {
    uint32_t a;
    asm("{ .reg .u64 t; cvta.to.shared.u64 t, %1; cvt.u32.u64 %0, t; }" : "=r"(a) : "l"(p));
    return a;
}
__device__ __forceinline__ void ffma2(unsigned long long& d, unsigned long long a, unsigned long long b) {
    asm("fma.rn.f32x2 %0, %1, %2, %0;" : "+l"(d) : "l"(a), "l"(b));
}
__device__ __forceinline__ unsigned long long pk2(float v) {
    unsigned long long r; asm("mov.b64 %0, {%1, %1};" : "=l"(r) : "f"(v)); return r;
}
__device__ __forceinline__ void up2(unsigned long long v, float& lo, float& hi) {
    asm("mov.b64 {%0, %1}, %2;" : "=f"(lo), "=f"(hi) : "l"(v));
}
#define CP16(dst, src)  asm volatile("cp.async.cg.shared.global [%0], [%1], 16;" :: "r"((uint32_t)(dst)), "l"(src) : "memory")
#define CP_COMMIT()     asm volatile("cp.async.commit_group;" ::: "memory")
#define CP_WAIT(n)      asm volatile("cp.async.wait_group %0;" :: "n"(n) : "memory")

__device__ __forceinline__ void ldsm4t(uint32_t& r0, uint32_t& r1, uint32_t& r2, uint32_t& r3, uint32_t a) {
    asm volatile("ldmatrix.sync.aligned.m8n8.x4.trans.shared.b16 {%0,%1,%2,%3}, [%4];"
                 : "=r"(r0), "=r"(r1), "=r"(r2), "=r"(r3) : "r"(a));
}
__device__ __forceinline__ void ldsm2(uint32_t& r0, uint32_t& r1, uint32_t a) {
    asm volatile("ldmatrix.sync.aligned.m8n8.x2.shared.b16 {%0,%1}, [%2];"
                 : "=r"(r0), "=r"(r1) : "r"(a));
}
__device__ __forceinline__ void mma16816(float* c, uint32_t a0, uint32_t a1, uint32_t a2, uint32_t a3,
                                         uint32_t b0, uint32_t b1) {
    asm volatile("mma.sync.aligned.m16n8k16.row.col.f32.f16.f16.f32 "
                 "{%0,%1,%2,%3}, {%4,%5,%6,%7}, {%8,%9}, {%0,%1,%2,%3};"
                 : "+f"(c[0]), "+f"(c[1]), "+f"(c[2]), "+f"(c[3])
                 : "r"(a0), "r"(a1), "r"(a2), "r"(a3), "r"(b0), "r"(b1));
}

// ---------------------------------------------------------------------------
// prep: jw3[f][h][k] -> g_Bt[f][k][h] fp16, pitch 272B. One block per f.
// ---------------------------------------------------------------------------
__global__ __launch_bounds__(256) void prep_kernel(const float* __restrict__ jw3) {
    extern __shared__ char psm[];   // 34816
    const int f = blockIdx.x, tid = threadIdx.x;
    const int h = tid >> 1, khalf = tid & 1;
    #pragma unroll 4
    for (int j = 0; j < 16; j++) {
        float4 v = *(const float4*)(jw3 + f * 16384 + h * 128 + khalf * 64 + j * 4);
        int k0 = khalf * 64 + j * 4;
        float vv[4] = {v.x, v.y, v.z, v.w};
        #pragma unroll
        for (int e = 0; e < 4; e++)
            *(__half*)(psm + (k0 + e) * BPITCH + h * 2) = __float2half_rn(vv[e]);
    }
    __syncthreads();
    float4* dst = (float4*)(g_Bt + f * SLAB);
    const float4* src = (const float4*)psm;
    #pragma unroll
    for (int i = 0; i < 9; i++) {
        int idx = tid + i * 256;
        if (idx < 2176) dst[idx] = src[idx];
    }
}

// ---------------------------------------------------------------------------
// gating: grid 128 x 256, 64 rows each -> raw logits g_gbuf
// ---------------------------------------------------------------------------
__global__ __launch_bounds__(256) void gating_kernel(
    const float* __restrict__ x, const float* __restrict__ s,
    const float* __restrict__ w1, const float* __restrict__ b1,
    const float* __restrict__ w2, const float* __restrict__ b2,
    const float* __restrict__ w3, const float* __restrict__ b3)
{
    extern __shared__ float gm[];
    float* xT = gm;            // [64 f][64 r]
    float* sT = gm + 4096;
    float* G1T = gm + 8192;    // [128 h][72]
    const int tid = threadIdx.x;
    const int rbase = blockIdx.x * 64;
    const int ty = tid >> 4, tx = tid & 15;

    #pragma unroll
    for (int i = 0; i < 4; i++) {
        int q = tid + i * 256;
        int r = q >> 4, fc = q & 15;
        float4 xv = *(const float4*)(x + (rbase + r) * FF + fc * 4);
        float4 sv = *(const float4*)(s + (rbase + r) * FF + fc * 4);
        xT[(fc * 4 + 0) * 64 + r] = xv.x; xT[(fc * 4 + 1) * 64 + r] = xv.y;
        xT[(fc * 4 + 2) * 64 + r] = xv.z; xT[(fc * 4 + 3) * 64 + r] = xv.w;
        sT[(fc * 4 + 0) * 64 + r] = sv.x; sT[(fc * 4 + 1) * 64 + r] = sv.y;
        sT[(fc * 4 + 2) * 64 + r] = sv.z; sT[(fc * 4 + 3) * 64 + r] = sv.w;
    }
    __syncthreads();

    unsigned long long acc[2][8];
    #pragma unroll
    for (int i = 0; i < 2; i++)
        #pragma unroll
        for (int j = 0; j < 8; j++) acc[i][j] = 0ull;

    #pragma unroll 4
    for (int f = 0; f < FF; f++) {
        ulonglong2 xv = *(const ulonglong2*)(xT + f * 64 + ty * 4);
        ulonglong2 sv = *(const ulonglong2*)(sT + f * 64 + ty * 4);
        float4 wa = *(const float4*)(w1 + f * HH + tx * 8);
        float4 wb = *(const float4*)(w1 + f * HH + tx * 8 + 4);
        float4 va = *(const float4*)(w2 + f * HH + tx * 8);
        float4 vb = *(const float4*)(w2 + f * HH + tx * 8 + 4);
        float ws[8] = {wa.x, wa.y, wa.z, wa.w, wb.x, wb.y, wb.z, wb.w};
        float vs[8] = {va.x, va.y, va.z, va.w, vb.x, vb.y, vb.z, vb.w};
        unsigned long long xp[2] = {xv.x, xv.y}, sp[2] = {sv.x, sv.y};
        #pragma unroll
        for (int j = 0; j < 8; j++) {
            unsigned long long wj = pk2(ws[j]), vj = pk2(vs[j]);
            #pragma unroll
            for (int i = 0; i < 2; i++) { ffma2(acc[i][j], xp[i], wj); ffma2(acc[i][j], sp[i], vj); }
        }
    }
    #pragma unroll
    for (int j = 0; j < 8; j++) {
        int h = tx * 8 + j;
        float bb = b1[h] + b2[h];
        float v[4];
        up2(acc[0][j], v[0], v[1]); up2(acc[1][j], v[2], v[3]);
        float4 o; float* po = &o.x;
        #pragma unroll
        for (int i = 0; i < 4; i++) {
            float t = v[i] + bb;
            po[i] = t > 0.f ? t : (__expf(t) - 1.f);
        }
        *(float4*)(G1T + h * 72 + ty * 4) = o;
    }
    __syncthreads();

    unsigned long long a2[2][4];
    #pragma unroll
    for (int i = 0; i < 2; i++)
        #pragma unroll
        for (int j = 0; j < 4; j++) a2[i][j] = 0ull;
    #pragma unroll 4
    for (int h = 0; h < HH; h++) {
        ulonglong2 av = *(const ulonglong2*)(G1T + h * 72 + ty * 4);
        float4 wv = *(const float4*)(w3 + h * FF + tx * 4);
        float ws[4] = {wv.x, wv.y, wv.z, wv.w};
        unsigned long long ap[2] = {av.x, av.y};
        #pragma unroll
        for (int j = 0; j < 4; j++) {
            unsigned long long wj = pk2(ws[j]);
            ffma2(a2[0][j], ap[0], wj);
            ffma2(a2[1][j], ap[1], wj);
        }
    }
    float b3v[4] = {b3[tx * 4], b3[tx * 4 + 1], b3[tx * 4 + 2], b3[tx * 4 + 3]};
    #pragma unroll
    for (int p = 0; p < 2; p++) {
        float lo[4], hi[4];
        #pragma unroll
        for (int j = 0; j < 4; j++) up2(a2[p][j], lo[j], hi[j]);
        int r0 = rbase + ty * 4 + p * 2;
        *(float4*)(g_gbuf + r0 * FF + tx * 4) =
            make_float4(lo[0] + b3v[0], lo[1] + b3v[1], lo[2] + b3v[2], lo[3] + b3v[3]);
        *(float4*)(g_gbuf + (r0 + 1) * FF + tx * 4) =
            make_float4(hi[0] + b3v[0], hi[1] + b3v[1], hi[2] + b3v[2], hi[3] + b3v[3]);
    }
}

// ---------------------------------------------------------------------------
// combine: warp-mma split-fp16. Grid 128 = 64 row-tiles x 2 f-halves.
// ---------------------------------------------------------------------------
#define AHI_OFF 0u
#define ALO_OFF 34816u
#define B0_OFF  69632u
#define XS_OFF  139264u
#define WT_OFF  155648u
#define JWC_OFF 172032u
#define SMEM2   173056u

__global__ __launch_bounds__(256, 1) void combine_kernel(
    const float* __restrict__ x,
    const float* __restrict__ jw1, const float* __restrict__ jb1,
    float* __restrict__ out)
{
    extern __shared__ char cm[];
    const uint32_t smb = smem_u32(cm);
    float* xs  = (float*)(cm + XS_OFF);    // [32 f][128 r]
    float* wts = (float*)(cm + WT_OFF);    // [32 f][128 r]
    float* jwc = (float*)(cm + JWC_OFF);   // interleaved jw1/jb1
    const int tid = threadIdx.x;
    const int wid = tid >> 5, lane = tid & 31;
    const int rt = blockIdx.x >> 1, half = blockIdx.x & 1;
    const int rbase = rt * 128, fbase = half * FH;
    float* dst = half ? g_part : out;

    // issue B(0) copy first
    {
        const unsigned char* src = g_Bt + fbase * SLAB;
        #pragma unroll
        for (int i = 0; i < 9; i++) {
            int idx = tid + i * 256;
            if (idx < 2176) CP16(smb + B0_OFF + idx * 16, src + idx * 16);
        }
        CP_COMMIT();
    }
    // stage x + raw G transposed [f][r]
    #pragma unroll
    for (int i = 0; i < 4; i++) {
        int q = tid + i * 256;
        int r = q >> 3, fs = q & 7;
        float4 xv = *(const float4*)(x      + (rbase + r) * FF + fbase + fs * 4);
        float4 gv = *(const float4*)(g_gbuf + (rbase + r) * FF + fbase + fs * 4);
        xs[(fs * 4 + 0) * 128 + r] = xv.x; xs[(fs * 4 + 1) * 128 + r] = xv.y;
        xs[(fs * 4 + 2) * 128 + r] = xv.z; xs[(fs * 4 + 3) * 128 + r] = xv.w;
        wts[(fs * 4 + 0) * 128 + r] = gv.x; wts[(fs * 4 + 1) * 128 + r] = gv.y;
        wts[(fs * 4 + 2) * 128 + r] = gv.z; wts[(fs * 4 + 3) * 128 + r] = gv.w;
    }
    __syncthreads();

    // softmax over the 128 rows per local f (32 f x 8 lanes)
    {
        const int fc = tid >> 3, sub = tid & 7;
        float vals[16], m = -1e30f;
        #pragma unroll
        for (int j = 0; j < 16; j++) {
            vals[j] = wts[fc * 128 + sub * 16 + j];
            m = fmaxf(m, vals[j]);
        }
        #pragma unroll
        for (int o = 1; o < 8; o <<= 1) m = fmaxf(m, __shfl_xor_sync(0xffffffffu, m, o, 8));
        float ssum = 0.f;
        #pragma unroll
        for (int j = 0; j < 16; j++) { vals[j] = __expf(vals[j] - m); ssum += vals[j]; }
        #pragma unroll
        for (int o = 1; o < 8; o <<= 1) ssum += __shfl_xor_sync(0xffffffffu, ssum, o, 8);
        float rinv = 1.f / ssum;
        #pragma unroll
        for (int j = 0; j < 16; j++) {
            int r = sub * 16 + j;
            float w = vals[j] * rinv;
            wts[fc * 128 + r] = w;
            g_wt_buf[(rbase + r) * FF + fbase + fc] = w;
        }
    }
    if (tid < 128) {
        jwc[2 * tid]     = jw1[fbase * HH + tid];
        jwc[2 * tid + 1] = jb1[fbase * HH + tid];
    }
    __syncthreads();

    const int rp = tid & 63, hblk = tid >> 6;

    // build A(0)
    {
        float xv0 = xs[0 * 128 + 2 * rp], xv1 = xs[0 * 128 + 2 * rp + 1];
        float wt0 = wts[0 * 128 + 2 * rp], wt1 = wts[0 * 128 + 2 * rp + 1];
        #pragma unroll 8
        for (int j = 0; j < 32; j++) {
            int h = hblk * 32 + j;
            float2 jv = *(const float2*)(jwc + 2 * h);
            float v0 = fmaf(xv0, jv.x, jv.y);
            float v1 = fmaf(xv1, jv.x, jv.y);
            float a0 = (v0 > 0.f ? v0 : (__expf(v0) - 1.f)) * wt0;
            float a1 = (v1 > 0.f ? v1 : (__expf(v1) - 1.f)) * wt1;
            __half2 hh = __float22half2_rn(make_float2(a0, a1));
            float2 bk = __half22float2(hh);
            __half2 ll = __float22half2_rn(make_float2(a0 - bk.x, a1 - bk.y));
            *(__half2*)(cm + AHI_OFF + h * BPITCH + rp * 4) = hh;
            *(__half2*)(cm + ALO_OFF + h * BPITCH + rp * 4) = ll;
        }
    }

    // MMA lane geometry
    const int m0 = wid * 16;
    const int lr = lane & 7, sel0 = (lane >> 3) & 1, sel1 = (lane >> 4) & 1;
    const uint32_t aHiBase = smb + AHI_OFF + m0 * 2 + (uint32_t)(sel1 * 8 + lr) * BPITCH + sel0 * 16;
    const uint32_t aLoBase = aHiBase + 34816u;
    const int l16 = lane & 15;
    const uint32_t bLane = (uint32_t)(l16 & 7) * BPITCH + ((l16 >> 3) & 1) * 16;

    float c[16][4];
    #pragma unroll
    for (int n = 0; n < 16; n++)
        #pragma unroll
        for (int e = 0; e < 4; e++) c[n][e] = 0.f;

    for (int fl = 0; fl < FH; fl++) {
        if (fl + 1 < FH) {
            const unsigned char* src = g_Bt + (fbase + fl + 1) * SLAB;
            uint32_t dstb = smb + B0_OFF + ((fl + 1) & 1) * SLAB;
            #pragma unroll
            for (int i = 0; i < 9; i++) {
                int idx = tid + i * 256;
                if (idx < 2176) CP16(dstb + idx * 16, src + idx * 16);
            }
            CP_COMMIT();
            CP_WAIT(1);
        } else {
            CP_WAIT(0);
        }
        __syncthreads();   // A(fl) built + B(fl) visible

        if (fl + 1 < FH && tid < 128) {
            jwc[2 * tid]     = jw1[(fbase + fl + 1) * HH + tid];
            jwc[2 * tid + 1] = jb1[(fbase + fl + 1) * HH + tid];
        }

        {
            const uint32_t bBase = smb + B0_OFF + (fl & 1) * SLAB + bLane;
            #pragma unroll
            for (int k = 0; k < 8; k++) {
                uint32_t ah0, ah1, ah2, ah3, al0, al1, al2, al3;
                ldsm4t(ah0, ah1, ah2, ah3, aHiBase + k * (16 * BPITCH));
                ldsm4t(al0, al1, al2, al3, aLoBase + k * (16 * BPITCH));
                #pragma unroll
                for (int n = 0; n < 16; n++) {
                    uint32_t b0, b1;
                    ldsm2(b0, b1, bBase + n * (8 * BPITCH) + k * 32);
                    mma16816(c[n], ah0, ah1, ah2, ah3, b0, b1);
                    mma16816(c[n], al0, al1, al2, al3, b0, b1);
                }
            }
        }
        __syncthreads();   // all warps done reading A(fl)

        if (fl + 1 < FH) {
            float xv0 = xs[(fl + 1) * 128 + 2 * rp], xv1 = xs[(fl + 1) * 128 + 2 * rp + 1];
            float wt0 = wts[(fl + 1) * 128 + 2 * rp], wt1 = wts[(fl + 1) * 128 + 2 * rp + 1];
            #pragma unroll 8
            for (int j = 0; j < 32; j++) {
                int h = hblk * 32 + j;
                float2 jv = *(const float2*)(jwc + 2 * h);
                float v0 = fmaf(xv0, jv.x, jv.y);
                float v1 = fmaf(xv1, jv.x, jv.y);
                float a0 = (v0 > 0.f ? v0 : (__expf(v0) - 1.f)) * wt0;
                float a1 = (v1 > 0.f ? v1 : (__expf(v1) - 1.f)) * wt1;
                __half2 hh = __float22half2_rn(make_float2(a0, a1));
                float2 bk = __half22float2(hh);
                __half2 ll = __float22half2_rn(make_float2(a0 - bk.x, a1 - bk.y));
                *(__half2*)(cm + AHI_OFF + h * BPITCH + rp * 4) = hh;
                *(__half2*)(cm + ALO_OFF + h * BPITCH + rp * 4) = ll;
            }
        }
    }

    {
        const int g = lane >> 2, tig = lane & 3;
        const int row0 = rbase + m0 + g;
        #pragma unroll
        for (int n = 0; n < 16; n++) {
            int col = n * 8 + 2 * tig;
            *(float2*)(dst + row0 * HH + col)       = make_float2(c[n][0], c[n][1]);
            *(float2*)(dst + (row0 + 8) * HH + col) = make_float2(c[n][2], c[n][3]);
        }
    }
}

// ---------------------------------------------------------------------------
// finish: out += g_part + w_t @ jb3. Grid 128 x 256, 64 rows each (FIXED).
// ---------------------------------------------------------------------------
__global__ __launch_bounds__(256) void finish_kernel(const float* __restrict__ jb3,
                                                     float* __restrict__ out)
{
    extern __shared__ float fm[];
    float* wtT  = fm;          // [64 f][64 r] = 4096
    float* jb3s = fm + 4096;   // [64 f][128 k] = 8192
    const int tid = threadIdx.x;
    const int rbase = blockIdx.x * 64;
    const int ty = tid >> 4, tx = tid & 15;

    #pragma unroll
    for (int i = 0; i < 4; i++) {
        int q = tid + i * 256;          // 0..1023
        int r = q >> 4, fc = q & 15;
        float4 wv = *(const float4*)(g_wt_buf + (rbase + r) * FF + fc * 4);
        wtT[(fc * 4 + 0) * 64 + r] = wv.x; wtT[(fc * 4 + 1) * 64 + r] = wv.y;
        wtT[(fc * 4 + 2) * 64 + r] = wv.z; wtT[(fc * 4 + 3) * 64 + r] = wv.w;
    }
    #pragma unroll
    for (int i = 0; i < 8; i++)
        ((float4*)jb3s)[tid + i * 256] = ((const float4*)jb3)[tid + i * 256];
    __syncthreads();

    unsigned long long acc[2][8];
    #pragma unroll
    for (int i = 0; i < 2; i++)
        #pragma unroll
        for (int j = 0; j < 8; j++) acc[i][j] = 0ull;
    #pragma unroll 4
    for (int f = 0; f < FF; f++) {
        ulonglong2 wv = *(const ulonglong2*)(wtT + f * 64 + ty * 4);
        float4 ja = *(const float4*)(jb3s + f * 128 + tx * 8);
        float4 jb = *(const float4*)(jb3s + f * 128 + tx * 8 + 4);
        float js[8] = {ja.x, ja.y, ja.z, ja.w, jb.x, jb.y, jb.z, jb.w};
        unsigned long long wp[2] = {wv.x, wv.y};
        #pragma unroll
        for (int j = 0; j < 8; j++) {
            unsigned long long jj = pk2(js[j]);
            ffma2(acc[0][j], wp[0], jj);
            ffma2(acc[1][j], wp[1], jj);
        }
    }
    #pragma unroll
    for (int p = 0; p < 2; p++) {
        float lo[8], hi[8];
        #pragma unroll
        for (int j = 0; j < 8; j++) up2(acc[p][j], lo[j], hi[j]);
        #pragma unroll
        for (int e = 0; e < 2; e++) {
            float* v = e ? hi : lo;
            int row = rbase + ty * 4 + p * 2 + e;
            float4* po = (float4*)(out + row * HH + tx * 8);
            const float4* pp = (const float4*)(g_part + row * HH + tx * 8);
            float4 o0 = po[0], o1 = po[1], p0 = pp[0], p1 = pp[1];
            po[0] = make_float4(o0.x + p0.x + v[0], o0.y + p0.y + v[1], o0.z + p0.z + v[2], o0.w + p0.w + v[3]);
            po[1] = make_float4(o1.x + p1.x + v[4], o1.y + p1.y + v[5], o1.z + p1.z + v[6], o1.w + p1.w + v[7]);
        }
    }
}

extern "C" void kernel_launch(void* const* d_in, const int* in_sizes, int n_in,
                              void* d_out, int out_size) {
    const float* x   = (const float*)d_in[0];
    const float* s   = (const float*)d_in[1];
    const float* w1  = (const float*)d_in[2];
    const float* b1  = (const float*)d_in[3];
    const float* w2  = (const float*)d_in[4];
    const float* b2  = (const float*)d_in[5];
    const float* w3  = (const float*)d_in[6];
    const float* b3  = (const float*)d_in[7];
    const float* jw1 = (const float*)d_in[8];
    const float* jb1 = (const float*)d_in[9];
    const float* jw3 = (const float*)d_in[10];
    const float* jb3 = (const float*)d_in[11];
    float* out = (float*)d_out;

    cudaFuncSetAttribute(prep_kernel,    cudaFuncAttributeMaxDynamicSharedMemorySize, SLAB);
    cudaFuncSetAttribute(gating_kernel,  cudaFuncAttributeMaxDynamicSharedMemorySize, 70016);
    cudaFuncSetAttribute(combine_kernel, cudaFuncAttributeMaxDynamicSharedMemorySize, SMEM2);
    cudaFuncSetAttribute(finish_kernel,  cudaFuncAttributeMaxDynamicSharedMemorySize, 49152);

    prep_kernel<<<64, 256, SLAB>>>(jw3);
    gating_kernel<<<128, 256, 70016>>>(x, s, w1, b1, w2, b2, w3, b3);
    combine_kernel<<<128, 256, SMEM2>>>(x, jw1, jb1, out);
    finish_kernel<<<128, 256, 49152>>>(jb3, out);
}

// round 7
// speedup vs baseline: 4.8581x; 1.2405x over previous
#include <cuda_runtime.h>
#include <cuda_fp16.h>
#include <stdint.h>

#define FF 64
#define HH 128
#define NROW 8192
#define FH 32
#define BPITCH 272            // bytes per 128-elem fp16 row (16B padded)
#define SLAB 34816            // 128 rows * 272 B

__device__ float g_gbuf[NROW * FF];     // raw gating logits
__device__ float g_wt_buf[NROW * FF];   // softmaxed gates
__device__ float g_part[NROW * HH];     // f-half-1 partial
__device__ __align__(16) unsigned char g_Bt[FF * SLAB];  // jw3^T fp16 [f][k][h]

// ---------------- helpers ----------------
__device__ __forceinline__ uint32_t smem_u32(const void* p) {
    uint32_t a;
    asm("{ .reg .u64 t; cvta.to.shared.u64 t, %1; cvt.u32.u64 %0, t; }" : "=r"(a) : "l"(p));
    return a;
}
__device__ __forceinline__ void ffma2(unsigned long long& d, unsigned long long a, unsigned long long b) {
    asm("fma.rn.f32x2 %0, %1, %2, %0;" : "+l"(d) : "l"(a), "l"(b));
}
__device__ __forceinline__ unsigned long long pk2(float v) {
    unsigned long long r; asm("mov.b64 %0, {%1, %1};" : "=l"(r) : "f"(v)); return r;
}
__device__ __forceinline__ void up2(unsigned long long v, float& lo, float& hi) {
    asm("mov.b64 {%0, %1}, %2;" : "=f"(lo), "=f"(hi) : "l"(v));
}
#define CP16(dst, src)  asm volatile("cp.async.cg.shared.global [%0], [%1], 16;" :: "r"((uint32_t)(dst)), "l"(src) : "memory")
#define CP_COMMIT()     asm volatile("cp.async.commit_group;" ::: "memory")
#define CP_WAIT(n)      asm volatile("cp.async.wait_group %0;" :: "n"(n) : "memory")

__device__ __forceinline__ void ldsm4t(uint32_t& r0, uint32_t& r1, uint32_t& r2, uint32_t& r3, uint32_t a) {
    asm volatile("ldmatrix.sync.aligned.m8n8.x4.trans.shared.b16 {%0,%1,%2,%3}, [%4];"
                 : "=r"(r0), "=r"(r1), "=r"(r2), "=r"(r3) : "r"(a));
}
__device__ __forceinline__ void ldsm2(uint32_t& r0, uint32_t& r1, uint32_t a) {
    asm volatile("ldmatrix.sync.aligned.m8n8.x2.shared.b16 {%0,%1}, [%2];"
                 : "=r"(r0), "=r"(r1) : "r"(a));
}
__device__ __forceinline__ void mma16816(float* c, uint32_t a0, uint32_t a1, uint32_t a2, uint32_t a3,
                                         uint32_t b0, uint32_t b1) {
    asm volatile("mma.sync.aligned.m16n8k16.row.col.f32.f16.f16.f32 "
                 "{%0,%1,%2,%3}, {%4,%5,%6,%7}, {%8,%9}, {%0,%1,%2,%3};"
                 : "+f"(c[0]), "+f"(c[1]), "+f"(c[2]), "+f"(c[3])
                 : "r"(a0), "r"(a1), "r"(a2), "r"(a3), "r"(b0), "r"(b1));
}

// ---------------------------------------------------------------------------
// prep: jw3[f][h][k] -> g_Bt[f][k][h] fp16, pitch 272B. One block per f.
// ---------------------------------------------------------------------------
__global__ __launch_bounds__(256) void prep_kernel(const float* __restrict__ jw3) {
    extern __shared__ char psm[];   // 34816
    const int f = blockIdx.x, tid = threadIdx.x;
    const int h = tid >> 1, khalf = tid & 1;
    #pragma unroll 4
    for (int j = 0; j < 16; j++) {
        float4 v = *(const float4*)(jw3 + f * 16384 + h * 128 + khalf * 64 + j * 4);
        int k0 = khalf * 64 + j * 4;
        float vv[4] = {v.x, v.y, v.z, v.w};
        #pragma unroll
        for (int e = 0; e < 4; e++)
            *(__half*)(psm + (k0 + e) * BPITCH + h * 2) = __float2half_rn(vv[e]);
    }
    __syncthreads();
    float4* dst = (float4*)(g_Bt + f * SLAB);
    const float4* src = (const float4*)psm;
    #pragma unroll
    for (int i = 0; i < 9; i++) {
        int idx = tid + i * 256;
        if (idx < 2176) dst[idx] = src[idx];
    }
}

// ---------------------------------------------------------------------------
// gating: grid 128 x 256, 64 rows each -> raw logits g_gbuf
// ---------------------------------------------------------------------------
__global__ __launch_bounds__(256) void gating_kernel(
    const float* __restrict__ x, const float* __restrict__ s,
    const float* __restrict__ w1, const float* __restrict__ b1,
    const float* __restrict__ w2, const float* __restrict__ b2,
    const float* __restrict__ w3, const float* __restrict__ b3)
{
    extern __shared__ float gm[];
    float* xT = gm;            // [64 f][64 r]
    float* sT = gm + 4096;
    float* G1T = gm + 8192;    // [128 h][72]
    const int tid = threadIdx.x;
    const int rbase = blockIdx.x * 64;
    const int ty = tid >> 4, tx = tid & 15;

    #pragma unroll
    for (int i = 0; i < 4; i++) {
        int q = tid + i * 256;
        int r = q >> 4, fc = q & 15;
        float4 xv = *(const float4*)(x + (rbase + r) * FF + fc * 4);
        float4 sv = *(const float4*)(s + (rbase + r) * FF + fc * 4);
        xT[(fc * 4 + 0) * 64 + r] = xv.x; xT[(fc * 4 + 1) * 64 + r] = xv.y;
        xT[(fc * 4 + 2) * 64 + r] = xv.z; xT[(fc * 4 + 3) * 64 + r] = xv.w;
        sT[(fc * 4 + 0) * 64 + r] = sv.x; sT[(fc * 4 + 1) * 64 + r] = sv.y;
        sT[(fc * 4 + 2) * 64 + r] = sv.z; sT[(fc * 4 + 3) * 64 + r] = sv.w;
    }
    __syncthreads();

    unsigned long long acc[2][8];
    #pragma unroll
    for (int i = 0; i < 2; i++)
        #pragma unroll
        for (int j = 0; j < 8; j++) acc[i][j] = 0ull;

    #pragma unroll 4
    for (int f = 0; f < FF; f++) {
        ulonglong2 xv = *(const ulonglong2*)(xT + f * 64 + ty * 4);
        ulonglong2 sv = *(const ulonglong2*)(sT + f * 64 + ty * 4);
        float4 wa = *(const float4*)(w1 + f * HH + tx * 8);
        float4 wb = *(const float4*)(w1 + f * HH + tx * 8 + 4);
        float4 va = *(const float4*)(w2 + f * HH + tx * 8);
        float4 vb = *(const float4*)(w2 + f * HH + tx * 8 + 4);
        float ws[8] = {wa.x, wa.y, wa.z, wa.w, wb.x, wb.y, wb.z, wb.w};
        float vs[8] = {va.x, va.y, va.z, va.w, vb.x, vb.y, vb.z, vb.w};
        unsigned long long xp[2] = {xv.x, xv.y}, sp[2] = {sv.x, sv.y};
        #pragma unroll
        for (int j = 0; j < 8; j++) {
            unsigned long long wj = pk2(ws[j]), vj = pk2(vs[j]);
            #pragma unroll
            for (int i = 0; i < 2; i++) { ffma2(acc[i][j], xp[i], wj); ffma2(acc[i][j], sp[i], vj); }
        }
    }
    #pragma unroll
    for (int j = 0; j < 8; j++) {
        int h = tx * 8 + j;
        float bb = b1[h] + b2[h];
        float v[4];
        up2(acc[0][j], v[0], v[1]); up2(acc[1][j], v[2], v[3]);
        float4 o; float* po = &o.x;
        #pragma unroll
        for (int i = 0; i < 4; i++) {
            float t = v[i] + bb;
            po[i] = t > 0.f ? t : (__expf(t) - 1.f);
        }
        *(float4*)(G1T + h * 72 + ty * 4) = o;
    }
    __syncthreads();

    unsigned long long a2[2][4];
    #pragma unroll
    for (int i = 0; i < 2; i++)
        #pragma unroll
        for (int j = 0; j < 4; j++) a2[i][j] = 0ull;
    #pragma unroll 4
    for (int h = 0; h < HH; h++) {
        ulonglong2 av = *(const ulonglong2*)(G1T + h * 72 + ty * 4);
        float4 wv = *(const float4*)(w3 + h * FF + tx * 4);
        float ws[4] = {wv.x, wv.y, wv.z, wv.w};
        unsigned long long ap[2] = {av.x, av.y};
        #pragma unroll
        for (int j = 0; j < 4; j++) {
            unsigned long long wj = pk2(ws[j]);
            ffma2(a2[0][j], ap[0], wj);
            ffma2(a2[1][j], ap[1], wj);
        }
    }
    float b3v[4] = {b3[tx * 4], b3[tx * 4 + 1], b3[tx * 4 + 2], b3[tx * 4 + 3]};
    #pragma unroll
    for (int p = 0; p < 2; p++) {
        float lo[4], hi[4];
        #pragma unroll
        for (int j = 0; j < 4; j++) up2(a2[p][j], lo[j], hi[j]);
        int r0 = rbase + ty * 4 + p * 2;
        *(float4*)(g_gbuf + r0 * FF + tx * 4) =
            make_float4(lo[0] + b3v[0], lo[1] + b3v[1], lo[2] + b3v[2], lo[3] + b3v[3]);
        *(float4*)(g_gbuf + (r0 + 1) * FF + tx * 4) =
            make_float4(hi[0] + b3v[0], hi[1] + b3v[1], hi[2] + b3v[2], hi[3] + b3v[3]);
    }
}

// ---------------------------------------------------------------------------
// combine: warp-mma fp16 (single product). Grid 128 = 64 row-tiles x 2 f-halves.
// smem: AHI 34816 | B 2x34816 | XS 16384 | WT 16384 | JWC 1024
// ---------------------------------------------------------------------------
#define AHI_OFF 0u
#define B0_OFF  34816u
#define XS_OFF  104448u
#define WT_OFF  120832u
#define JWC_OFF 137216u
#define SMEM2   138240u

__global__ __launch_bounds__(256, 1) void combine_kernel(
    const float* __restrict__ x,
    const float* __restrict__ jw1, const float* __restrict__ jb1,
    float* __restrict__ out)
{
    extern __shared__ char cm[];
    const uint32_t smb = smem_u32(cm);
    float* xs  = (float*)(cm + XS_OFF);    // [32 f][128 r]
    float* wts = (float*)(cm + WT_OFF);    // [32 f][128 r]
    float* jwc = (float*)(cm + JWC_OFF);   // interleaved jw1/jb1
    const int tid = threadIdx.x;
    const int wid = tid >> 5, lane = tid & 31;
    const int rt = blockIdx.x >> 1, half = blockIdx.x & 1;
    const int rbase = rt * 128, fbase = half * FH;
    float* dst = half ? g_part : out;

    // issue B(0) copy first
    {
        const unsigned char* src = g_Bt + fbase * SLAB;
        #pragma unroll
        for (int i = 0; i < 9; i++) {
            int idx = tid + i * 256;
            if (idx < 2176) CP16(smb + B0_OFF + idx * 16, src + idx * 16);
        }
        CP_COMMIT();
    }
    // stage x + raw G transposed [f][r]
    #pragma unroll
    for (int i = 0; i < 4; i++) {
        int q = tid + i * 256;
        int r = q >> 3, fs = q & 7;
        float4 xv = *(const float4*)(x      + (rbase + r) * FF + fbase + fs * 4);
        float4 gv = *(const float4*)(g_gbuf + (rbase + r) * FF + fbase + fs * 4);
        xs[(fs * 4 + 0) * 128 + r] = xv.x; xs[(fs * 4 + 1) * 128 + r] = xv.y;
        xs[(fs * 4 + 2) * 128 + r] = xv.z; xs[(fs * 4 + 3) * 128 + r] = xv.w;
        wts[(fs * 4 + 0) * 128 + r] = gv.x; wts[(fs * 4 + 1) * 128 + r] = gv.y;
        wts[(fs * 4 + 2) * 128 + r] = gv.z; wts[(fs * 4 + 3) * 128 + r] = gv.w;
    }
    __syncthreads();

    // softmax over the 128 rows per local f (32 f x 8 lanes)
    {
        const int fc = tid >> 3, sub = tid & 7;
        float vals[16], m = -1e30f;
        #pragma unroll
        for (int j = 0; j < 16; j++) {
            vals[j] = wts[fc * 128 + sub * 16 + j];
            m = fmaxf(m, vals[j]);
        }
        #pragma unroll
        for (int o = 1; o < 8; o <<= 1) m = fmaxf(m, __shfl_xor_sync(0xffffffffu, m, o, 8));
        float ssum = 0.f;
        #pragma unroll
        for (int j = 0; j < 16; j++) { vals[j] = __expf(vals[j] - m); ssum += vals[j]; }
        #pragma unroll
        for (int o = 1; o < 8; o <<= 1) ssum += __shfl_xor_sync(0xffffffffu, ssum, o, 8);
        float rinv = 1.f / ssum;
        #pragma unroll
        for (int j = 0; j < 16; j++) {
            int r = sub * 16 + j;
            float w = vals[j] * rinv;
            wts[fc * 128 + r] = w;
            g_wt_buf[(rbase + r) * FF + fbase + fc] = w;
        }
    }
    if (tid < 128) {
        jwc[2 * tid]     = jw1[fbase * HH + tid];
        jwc[2 * tid + 1] = jb1[fbase * HH + tid];
    }
    __syncthreads();

    const int rp = tid & 63, hblk = tid >> 6;

    // build A(0): Ahi[h][r] fp16
    {
        float xv0 = xs[0 * 128 + 2 * rp], xv1 = xs[0 * 128 + 2 * rp + 1];
        float wt0 = wts[0 * 128 + 2 * rp], wt1 = wts[0 * 128 + 2 * rp + 1];
        #pragma unroll 8
        for (int j = 0; j < 32; j++) {
            int h = hblk * 32 + j;
            float2 jv = *(const float2*)(jwc + 2 * h);
            float v0 = fmaf(xv0, jv.x, jv.y);
            float v1 = fmaf(xv1, jv.x, jv.y);
            float a0 = (v0 > 0.f ? v0 : (__expf(v0) - 1.f)) * wt0;
            float a1 = (v1 > 0.f ? v1 : (__expf(v1) - 1.f)) * wt1;
            *(__half2*)(cm + AHI_OFF + h * BPITCH + rp * 4) = __float22half2_rn(make_float2(a0, a1));
        }
    }

    // MMA lane geometry
    const int m0 = wid * 16;
    const int lr = lane & 7, sel0 = (lane >> 3) & 1, sel1 = (lane >> 4) & 1;
    const uint32_t aHiBase = smb + AHI_OFF + m0 * 2 + (uint32_t)(sel1 * 8 + lr) * BPITCH + sel0 * 16;
    const int l16 = lane & 15;
    const uint32_t bLane = (uint32_t)(l16 & 7) * BPITCH + ((l16 >> 3) & 1) * 16;

    float c[16][4];
    #pragma unroll
    for (int n = 0; n < 16; n++)
        #pragma unroll
        for (int e = 0; e < 4; e++) c[n][e] = 0.f;

    for (int fl = 0; fl < FH; fl++) {
        if (fl + 1 < FH) {
            const unsigned char* src = g_Bt + (fbase + fl + 1) * SLAB;
            uint32_t dstb = smb + B0_OFF + ((fl + 1) & 1) * SLAB;
            #pragma unroll
            for (int i = 0; i < 9; i++) {
                int idx = tid + i * 256;
                if (idx < 2176) CP16(dstb + idx * 16, src + idx * 16);
            }
            CP_COMMIT();
            CP_WAIT(1);
        } else {
            CP_WAIT(0);
        }
        __syncthreads();   // A(fl) built + B(fl) visible

        if (fl + 1 < FH && tid < 128) {
            jwc[2 * tid]     = jw1[(fbase + fl + 1) * HH + tid];
            jwc[2 * tid + 1] = jb1[(fbase + fl + 1) * HH + tid];
        }

        // MMA over f = fbase+fl: hoist A fragments, batch B loads
        {
            uint32_t a[8][4];
            #pragma unroll
            for (int k = 0; k < 8; k++)
                ldsm4t(a[k][0], a[k][1], a[k][2], a[k][3], aHiBase + (uint32_t)k * (16 * BPITCH));

            const uint32_t bBase = smb + B0_OFF + (fl & 1) * SLAB + bLane;
            #pragma unroll
            for (int np = 0; np < 8; np++) {
                // two n-tiles interleaved for independent accumulator chains
                uint32_t b0[8][2], b1v[8][2];
                const uint32_t nb0 = bBase + (uint32_t)(2 * np) * (8 * BPITCH);
                const uint32_t nb1 = nb0 + (uint32_t)(8 * BPITCH);
                #pragma unroll
                for (int k = 0; k < 8; k++) {
                    ldsm2(b0[k][0], b0[k][1], nb0 + (uint32_t)k * 32);
                    ldsm2(b1v[k][0], b1v[k][1], nb1 + (uint32_t)k * 32);
                }
                #pragma unroll
                for (int k = 0; k < 8; k++) {
                    mma16816(c[2 * np],     a[k][0], a[k][1], a[k][2], a[k][3], b0[k][0], b0[k][1]);
                    mma16816(c[2 * np + 1], a[k][0], a[k][1], a[k][2], a[k][3], b1v[k][0], b1v[k][1]);
                }
            }
        }
        __syncthreads();   // all warps done reading A(fl)

        // build A(fl+1)
        if (fl + 1 < FH) {
            float xv0 = xs[(fl + 1) * 128 + 2 * rp], xv1 = xs[(fl + 1) * 128 + 2 * rp + 1];
            float wt0 = wts[(fl + 1) * 128 + 2 * rp], wt1 = wts[(fl + 1) * 128 + 2 * rp + 1];
            #pragma unroll 8
            for (int j = 0; j < 32; j++) {
                int h = hblk * 32 + j;
                float2 jv = *(const float2*)(jwc + 2 * h);
                float v0 = fmaf(xv0, jv.x, jv.y);
                float v1 = fmaf(xv1, jv.x, jv.y);
                float a0 = (v0 > 0.f ? v0 : (__expf(v0) - 1.f)) * wt0;
                float a1 = (v1 > 0.f ? v1 : (__expf(v1) - 1.f)) * wt1;
                *(__half2*)(cm + AHI_OFF + h * BPITCH + rp * 4) = __float22half2_rn(make_float2(a0, a1));
            }
        }
    }

    {
        const int g = lane >> 2, tig = lane & 3;
        const int row0 = rbase + m0 + g;
        #pragma unroll
        for (int n = 0; n < 16; n++) {
            int col = n * 8 + 2 * tig;
            *(float2*)(dst + row0 * HH + col)       = make_float2(c[n][0], c[n][1]);
            *(float2*)(dst + (row0 + 8) * HH + col) = make_float2(c[n][2], c[n][3]);
        }
    }
}

// ---------------------------------------------------------------------------
// finish: out += g_part + w_t @ jb3. Grid 128 x 256, 64 rows each.
// ---------------------------------------------------------------------------
__global__ __launch_bounds__(256) void finish_kernel(const float* __restrict__ jb3,
                                                     float* __restrict__ out)
{
    extern __shared__ float fm[];
    float* wtT  = fm;          // [64 f][64 r] = 4096
    float* jb3s = fm + 4096;   // [64 f][128 k] = 8192
    const int tid = threadIdx.x;
    const int rbase = blockIdx.x * 64;
    const int ty = tid >> 4, tx = tid & 15;

    #pragma unroll
    for (int i = 0; i < 4; i++) {
        int q = tid + i * 256;          // 0..1023
        int r = q >> 4, fc = q & 15;
        float4 wv = *(const float4*)(g_wt_buf + (rbase + r) * FF + fc * 4);
        wtT[(fc * 4 + 0) * 64 + r] = wv.x; wtT[(fc * 4 + 1) * 64 + r] = wv.y;
        wtT[(fc * 4 + 2) * 64 + r] = wv.z; wtT[(fc * 4 + 3) * 64 + r] = wv.w;
    }
    #pragma unroll
    for (int i = 0; i < 8; i++)
        ((float4*)jb3s)[tid + i * 256] = ((const float4*)jb3)[tid + i * 256];
    __syncthreads();

    unsigned long long acc[2][8];
    #pragma unroll
    for (int i = 0; i < 2; i++)
        #pragma unroll
        for (int j = 0; j < 8; j++) acc[i][j] = 0ull;
    #pragma unroll 4
    for (int f = 0; f < FF; f++) {
        ulonglong2 wv = *(const ulonglong2*)(wtT + f * 64 + ty * 4);
        float4 ja = *(const float4*)(jb3s + f * 128 + tx * 8);
        float4 jb = *(const float4*)(jb3s + f * 128 + tx * 8 + 4);
        float js[8] = {ja.x, ja.y, ja.z, ja.w, jb.x, jb.y, jb.z, jb.w};
        unsigned long long wp[2] = {wv.x, wv.y};
        #pragma unroll
        for (int j = 0; j < 8; j++) {
            unsigned long long jj = pk2(js[j]);
            ffma2(acc[0][j], wp[0], jj);
            ffma2(acc[1][j], wp[1], jj);
        }
    }
    #pragma unroll
    for (int p = 0; p < 2; p++) {
        float lo[8], hi[8];
        #pragma unroll
        for (int j = 0; j < 8; j++) up2(acc[p][j], lo[j], hi[j]);
        #pragma unroll
        for (int e = 0; e < 2; e++) {
            float* v = e ? hi : lo;
            int row = rbase + ty * 4 + p * 2 + e;
            float4* po = (float4*)(out + row * HH + tx * 8);
            const float4* pp = (const float4*)(g_part + row * HH + tx * 8);
            float4 o0 = po[0], o1 = po[1], p0 = pp[0], p1 = pp[1];
            po[0] = make_float4(o0.x + p0.x + v[0], o0.y + p0.y + v[1], o0.z + p0.z + v[2], o0.w + p0.w + v[3]);
            po[1] = make_float4(o1.x + p1.x + v[4], o1.y + p1.y + v[5], o1.z + p1.z + v[6], o1.w + p1.w + v[7]);
        }
    }
}

extern "C" void kernel_launch(void* const* d_in, const int* in_sizes, int n_in,
                              void* d_out, int out_size) {
    const float* x   = (const float*)d_in[0];
    const float* s   = (const float*)d_in[1];
    const float* w1  = (const float*)d_in[2];
    const float* b1  = (const float*)d_in[3];
    const float* w2  = (const float*)d_in[4];
    const float* b2  = (const float*)d_in[5];
    const float* w3  = (const float*)d_in[6];
    const float* b3  = (const float*)d_in[7];
    const float* jw1 = (const float*)d_in[8];
    const float* jb1 = (const float*)d_in[9];
    const float* jw3 = (const float*)d_in[10];
    const float* jb3 = (const float*)d_in[11];
    float* out = (float*)d_out;

    cudaFuncSetAttribute(prep_kernel,    cudaFuncAttributeMaxDynamicSharedMemorySize, SLAB);
    cudaFuncSetAttribute(gating_kernel,  cudaFuncAttributeMaxDynamicSharedMemorySize, 70016);
    cudaFuncSetAttribute(combine_kernel, cudaFuncAttributeMaxDynamicSharedMemorySize, SMEM2);
    cudaFuncSetAttribute(finish_kernel,  cudaFuncAttributeMaxDynamicSharedMemorySize, 49152);

    prep_kernel<<<64, 256, SLAB>>>(jw3);
    gating_kernel<<<128, 256, 70016>>>(x, s, w1, b1, w2, b2, w3, b3);
    combine_kernel<<<128, 256, SMEM2>>>(x, jw1, jb1, out);
    finish_kernel<<<128, 256, 49152>>>(jb3, out);
}